// round 10
// baseline (speedup 1.0000x reference)
#include <cuda_runtime.h>
#include <cuda_fp16.h>
#include <cstdint>

#define T_LEN   4096
#define D_DIM   256
#define ATT     50
#define NPAD    64
#define CH      64      // rows per chunk
#define XH2     132     // fp16 x tile row stride in half2 units (132%32==4 -> conflict-free A loads)
#define WS2     56      // W half2 row stride (56%32==24 -> conflict-free B loads)
#define NBATCH  64
#define NCHUNK  (NBATCH * (T_LEN / CH))   // 4096
#define GRID    296     // 2 CTAs/SM x 148 SMs
#define EPS     1e-7f

// ---- SMEM byte offsets ----
#define XH_OFF   0                        // 2 x 64 x 132 half2 = 67584 B
#define WH_OFF   67584                    // 128 x 56 half2    = 28672 B
#define US_OFF   96256
#define BS_OFF   96512
#define ES_OFF   96768
#define P0_OFF   97024
#define P1_OFF   97280
#define SMEM_BYTES 97536                  // 95.25 KB -> 2 CTAs/SM

__device__ float   g_denom[NBATCH];
__device__ __half2 g_Wh2[128 * WS2];
__device__ float   g_up[NPAD];
__device__ float   g_bp[NPAD];

__device__ __forceinline__ float tanh_fast(float v) {
    float r;
    asm("tanh.approx.f32 %0, %1;" : "=f"(r) : "f"(v));
    return r;
}
__device__ __forceinline__ uint32_t h2u(__half2 h) {
    return *reinterpret_cast<uint32_t*>(&h);
}

__global__ void prep_kernel(const float* __restrict__ W,
                            const float* __restrict__ b,
                            const float* __restrict__ u,
                            float* __restrict__ out) {
    int i = blockIdx.x * blockDim.x + threadIdx.x;
    if (i < 128 * WS2) {
        int k2 = i / WS2, n = i % WS2;
        float w0 = (n < ATT) ? W[(2 * k2)     * ATT + n] : 0.0f;
        float w1 = (n < ATT) ? W[(2 * k2 + 1) * ATT + n] : 0.0f;
        g_Wh2[i] = __floats2half2_rn(w0, w1);
    }
    if (i < NPAD) {
        g_up[i] = (i < ATT) ? u[i] : 0.0f;
        g_bp[i] = (i < ATT) ? b[i] : 0.0f;
    }
    if (i < NBATCH) g_denom[i] = 0.0f;
    if (i < NBATCH * D_DIM) out[i] = 0.0f;
}

// Phase-2 worker: NT n-tiles starting at column cbase; x already fp16 in SMEM.
template<int NT>
__device__ __forceinline__ void phase2(const __half2* __restrict__ cur,
                                       const __half2* __restrict__ Wh,
                                       const float* __restrict__ us,
                                       const float* __restrict__ bs,
                                       float* __restrict__ pp,
                                       int mrow, int cbase, int g, int t) {
    float c[NT][4];
    #pragma unroll
    for (int nt = 0; nt < NT; nt++) {
        c[nt][0] = 0.f; c[nt][1] = 0.f; c[nt][2] = 0.f; c[nt][3] = 0.f;
    }
    const __half2* xr0 = cur + (mrow + g) * XH2;
    const __half2* xr1 = xr0 + 8 * XH2;

    #pragma unroll 4
    for (int k2 = 0; k2 < D_DIM / 2; k2 += 8) {
        uint32_t a0 = h2u(xr0[k2 + t]);
        uint32_t a1 = h2u(xr1[k2 + t]);
        uint32_t a2 = h2u(xr0[k2 + t + 4]);
        uint32_t a3 = h2u(xr1[k2 + t + 4]);
        const __half2* wk0 = Wh + (k2 + t) * WS2 + cbase;
        const __half2* wk1 = wk0 + 4 * WS2;
        #pragma unroll
        for (int nt = 0; nt < NT; nt++) {
            uint32_t b0 = h2u(wk0[nt * 8 + g]);
            uint32_t b1 = h2u(wk1[nt * 8 + g]);
            asm volatile(
                "mma.sync.aligned.m16n8k16.row.col.f32.f16.f16.f32 "
                "{%0,%1,%2,%3}, {%4,%5,%6,%7}, {%8,%9}, {%0,%1,%2,%3};"
                : "+f"(c[nt][0]), "+f"(c[nt][1]), "+f"(c[nt][2]), "+f"(c[nt][3])
                : "r"(a0), "r"(a1), "r"(a2), "r"(a3), "r"(b0), "r"(b1));
        }
    }

    float slo = 0.f, shi = 0.f;
    #pragma unroll
    for (int nt = 0; nt < NT; nt++) {
        int col = cbase + nt * 8 + 2 * t;
        float u0 = us[col], u1 = us[col + 1];
        float B0 = bs[col], B1 = bs[col + 1];
        slo += tanh_fast(c[nt][0] + B0) * u0 + tanh_fast(c[nt][1] + B1) * u1;
        shi += tanh_fast(c[nt][2] + B0) * u0 + tanh_fast(c[nt][3] + B1) * u1;
    }
    slo += __shfl_xor_sync(0xFFFFFFFFu, slo, 1);
    slo += __shfl_xor_sync(0xFFFFFFFFu, slo, 2);
    shi += __shfl_xor_sync(0xFFFFFFFFu, shi, 1);
    shi += __shfl_xor_sync(0xFFFFFFFFu, shi, 2);
    if (t == 0) {
        pp[mrow + g]     = slo;
        pp[mrow + g + 8] = shi;
    }
}

__global__ __launch_bounds__(256, 2)
void att_main_kernel(const float* __restrict__ x, float* __restrict__ out) {
    extern __shared__ char smem[];
    __half2* xh = (__half2*)(smem + XH_OFF);
    __half2* Wh = (__half2*)(smem + WH_OFF);
    float*   us = (float*)(smem + US_OFF);
    float*   bs = (float*)(smem + BS_OFF);
    float*   es = (float*)(smem + ES_OFF);
    float*   p0 = (float*)(smem + P0_OFF);
    float*   p1 = (float*)(smem + P1_OFF);

    const int tid  = threadIdx.x;
    const int lane = tid & 31;
    const int warp = tid >> 5;
    const int g = lane >> 2;
    const int t = lane & 3;
    const int mrow = (warp & 3) * 16;

    // ---- Stage x chunk: global fp32 -> SMEM fp16 (half2 pairs along k) ----
    auto stage = [&](int c, int bufidx) {
        const float4* xg = (const float4*)(x
            + ((size_t)(c >> 6) * T_LEN + (size_t)(c & 63) * CH) * D_DIM);
        __half2* dst = xh + bufidx * (CH * XH2);
        #pragma unroll 4
        for (int j = 0; j < 16; j++) {
            int i  = j * 256 + tid;
            int r  = i >> 6;
            int c4 = i & 63;
            float4 v = xg[i];
            uint2 h;
            h.x = h2u(__floats2half2_rn(v.x, v.y));
            h.y = h2u(__floats2half2_rn(v.z, v.w));
            *(uint2*)&dst[r * XH2 + c4 * 2] = h;
        }
    };

    // ---- Stage W (fp16, prepped) + vectors, and chunk 0 ----
    #pragma unroll
    for (int i = tid; i < 128 * WS2 / 4; i += 256)
        ((uint4*)Wh)[i] = ((const uint4*)g_Wh2)[i];
    if (tid < NPAD) { us[tid] = g_up[tid]; bs[tid] = g_bp[tid]; }

    const int c0 = blockIdx.x;
    stage(c0, 0);
    __syncthreads();

    int it = 0;
    for (int c = c0; c < NCHUNK; c += GRID, it++) {
        const int nb = it & 1;
        const int cn = c + GRID;
        const __half2* cur = xh + nb * (CH * XH2);
        const int b = c >> 6;

        // ---- Phase 2: fp16 MMA from SMEM fp16 x ----
        if (warp < 4) phase2<4>(cur, Wh, us, bs, p0, mrow, 0,  g, t);
        else          phase2<3>(cur, Wh, us, bs, p1, mrow, 32, g, t);
        __syncthreads();   // p0/p1 ready; cur fully consumed

        // ---- Stage next chunk into the other buffer (overlaps exp+phase3) ----
        if (cn < NCHUNK) stage(cn, nb ^ 1);

        // ---- exp + denominator (warp 0) ----
        if (warp == 0) {
            float e0 = __expf(p0[lane]      + p1[lane]);
            float e1 = __expf(p0[lane + 32] + p1[lane + 32]);
            es[lane]      = e0;
            es[lane + 32] = e1;
            float s = e0 + e1;
            #pragma unroll
            for (int o = 16; o > 0; o >>= 1) s += __shfl_xor_sync(0xFFFFFFFFu, s, o);
            if (lane == 0) atomicAdd(&g_denom[b], s);
        }
        __syncthreads();   // es ready; staging STS complete

        // ---- Phase 3: weighted sum with exact fp32 x from global (L2-hot) ----
        {
            const float* xg = x + ((size_t)b * T_LEN + (size_t)(c & 63) * CH) * D_DIM;
            float q0 = 0.f, q1 = 0.f, q2 = 0.f, q3 = 0.f;
            #pragma unroll 8
            for (int r = 0; r < CH; r += 4) {
                q0 += es[r + 0] * xg[(size_t)(r + 0) * D_DIM + tid];
                q1 += es[r + 1] * xg[(size_t)(r + 1) * D_DIM + tid];
                q2 += es[r + 2] * xg[(size_t)(r + 2) * D_DIM + tid];
                q3 += es[r + 3] * xg[(size_t)(r + 3) * D_DIM + tid];
            }
            atomicAdd(&out[b * D_DIM + tid], (q0 + q1) + (q2 + q3));
        }
        // no trailing sync needed: next phase2 reads buf nb^1 (staged before the
        // es-sync); p0/p1 rewritten only by phase2' whose consumers synced; es
        // rewritten only after the next phase2's barrier.
    }
}

__global__ void norm_kernel(float* __restrict__ out) {
    int i = blockIdx.x * blockDim.x + threadIdx.x;
    if (i < NBATCH * D_DIM) {
        out[i] = out[i] / (g_denom[i >> 8] + EPS);
    }
}

extern "C" void kernel_launch(void* const* d_in, const int* in_sizes, int n_in,
                              void* d_out, int out_size) {
    const float* x = (const float*)d_in[0];
    const float* W = (const float*)d_in[1];
    const float* b = (const float*)d_in[2];
    const float* u = (const float*)d_in[3];
    float* out = (float*)d_out;

    cudaFuncSetAttribute(att_main_kernel,
                         cudaFuncAttributeMaxDynamicSharedMemorySize, SMEM_BYTES);

    prep_kernel<<<(NBATCH * D_DIM + 255) / 256, 256>>>(W, b, u, out);
    att_main_kernel<<<GRID, 256, SMEM_BYTES>>>(x, out);
    norm_kernel<<<(NBATCH * D_DIM + 255) / 256, 256>>>(out);
}

// round 11
// speedup vs baseline: 1.0004x; 1.0004x over previous
#include <cuda_runtime.h>
#include <cuda_fp16.h>
#include <cstdint>

#define T_LEN   4096
#define D_DIM   256
#define ATT     50
#define NPAD    64
#define CH      32      // rows per chunk (half of R5 -> 2 CTAs/SM)
#define XS      264     // x row stride (floats): conflict-free LDS.64 A loads & phase-3 reads
#define WS2     56      // W half2 row stride: (24t+g)%32 distinct -> conflict-free B loads
#define NBATCH  64
#define CPB     (T_LEN / CH)              // 128 chunks per batch
#define NCHUNK  (NBATCH * CPB)            // 8192
#define GRID    296     // 148 SMs x 2 CTAs
#define EPS     1e-7f

__device__ float   g_denom[NBATCH];
__device__ __half2 g_Wh2[128 * WS2];   // fp16 W^T pairs along k, zero-padded n>=ATT
__device__ float   g_up[NPAD];
__device__ float   g_bp[NPAD];

__device__ __forceinline__ float tanh_fast(float v) {
    float r;
    asm("tanh.approx.f32 %0, %1;" : "=f"(r) : "f"(v));
    return r;
}
__device__ __forceinline__ uint32_t h2u(__half2 h) {
    return *reinterpret_cast<uint32_t*>(&h);
}

__global__ void prep_kernel(const float* __restrict__ W,
                            const float* __restrict__ b,
                            const float* __restrict__ u,
                            float* __restrict__ out) {
    int i = blockIdx.x * blockDim.x + threadIdx.x;
    if (i < 128 * WS2) {
        int k2 = i / WS2, n = i % WS2;
        float w0 = (n < ATT) ? W[(2 * k2)     * ATT + n] : 0.0f;
        float w1 = (n < ATT) ? W[(2 * k2 + 1) * ATT + n] : 0.0f;
        g_Wh2[i] = __floats2half2_rn(w0, w1);
    }
    if (i < NPAD) {
        g_up[i] = (i < ATT) ? u[i] : 0.0f;
        g_bp[i] = (i < ATT) ? b[i] : 0.0f;
    }
    if (i < NBATCH) g_denom[i] = 0.0f;
    if (i < NBATCH * D_DIM) out[i] = 0.0f;
}

// Phase-2 worker: NT n-tiles starting at column cbase, 16 rows starting at mrow.
// Writes per-column-group PARTIAL scores (tanh.u is separable across column groups).
template<int NT>
__device__ __forceinline__ void phase2(const float* __restrict__ cur,
                                       const __half2* __restrict__ Wh,
                                       const float* __restrict__ us,
                                       const float* __restrict__ bs,
                                       float* __restrict__ pp,   // partial[32 rows]
                                       int mrow, int cbase, int g, int t) {
    float c[NT][4];
    #pragma unroll
    for (int nt = 0; nt < NT; nt++) {
        c[nt][0] = 0.f; c[nt][1] = 0.f; c[nt][2] = 0.f; c[nt][3] = 0.f;
    }
    const float* xr0 = cur + (mrow + g) * XS;
    const float* xr1 = xr0 + 8 * XS;

    #pragma unroll 4
    for (int k0 = 0; k0 < D_DIM; k0 += 16) {
        float2 f0 = *(const float2*)&xr0[k0 + 2 * t];
        float2 f1 = *(const float2*)&xr1[k0 + 2 * t];
        float2 f2 = *(const float2*)&xr0[k0 + 2 * t + 8];
        float2 f3 = *(const float2*)&xr1[k0 + 2 * t + 8];
        uint32_t a0 = h2u(__floats2half2_rn(f0.x, f0.y));
        uint32_t a1 = h2u(__floats2half2_rn(f1.x, f1.y));
        uint32_t a2 = h2u(__floats2half2_rn(f2.x, f2.y));
        uint32_t a3 = h2u(__floats2half2_rn(f3.x, f3.y));
        const __half2* wk0 = Wh + ((k0 >> 1) + t) * WS2 + cbase;
        const __half2* wk1 = wk0 + 4 * WS2;
        #pragma unroll
        for (int nt = 0; nt < NT; nt++) {
            uint32_t b0 = h2u(wk0[nt * 8 + g]);
            uint32_t b1 = h2u(wk1[nt * 8 + g]);
            asm volatile(
                "mma.sync.aligned.m16n8k16.row.col.f32.f16.f16.f32 "
                "{%0,%1,%2,%3}, {%4,%5,%6,%7}, {%8,%9}, {%0,%1,%2,%3};"
                : "+f"(c[nt][0]), "+f"(c[nt][1]), "+f"(c[nt][2]), "+f"(c[nt][3])
                : "r"(a0), "r"(a1), "r"(a2), "r"(a3), "r"(b0), "r"(b1));
        }
    }

    float slo = 0.f, shi = 0.f;
    #pragma unroll
    for (int nt = 0; nt < NT; nt++) {
        int col = cbase + nt * 8 + 2 * t;
        float u0 = us[col], u1 = us[col + 1];
        float B0 = bs[col], B1 = bs[col + 1];
        slo += tanh_fast(c[nt][0] + B0) * u0 + tanh_fast(c[nt][1] + B1) * u1;
        shi += tanh_fast(c[nt][2] + B0) * u0 + tanh_fast(c[nt][3] + B1) * u1;
    }
    slo += __shfl_xor_sync(0xFFFFFFFFu, slo, 1);
    slo += __shfl_xor_sync(0xFFFFFFFFu, slo, 2);
    shi += __shfl_xor_sync(0xFFFFFFFFu, shi, 1);
    shi += __shfl_xor_sync(0xFFFFFFFFu, shi, 2);
    if (t == 0) {
        pp[mrow + g]     = slo;
        pp[mrow + g + 8] = shi;
    }
}

__global__ __launch_bounds__(256, 2)
void att_main_kernel(const float* __restrict__ x, float* __restrict__ out) {
    extern __shared__ float sm[];
    float*   xs  = sm;                              // 2 * CH * XS floats (67584 B)
    __half2* Wh  = (__half2*)(sm + 2 * CH * XS);    // 128 * WS2 half2   (28672 B)
    float*   us  = (float*)(Wh + 128 * WS2);        // NPAD
    float*   bs  = us + NPAD;                       // NPAD
    float*   es  = bs + NPAD;                       // CH (32)
    float*   pt  = es + CH;                         // 4 groups x 32 rows partials

    const int tid  = threadIdx.x;
    const int lane = tid & 31;
    const int warp = tid >> 5;
    const int g = lane >> 2;
    const int t = lane & 3;
    const int mrow  = (warp & 1) * 16;      // m-half: rows 0-15 or 16-31
    const int ngrp  = warp >> 1;            // column group 0..3
    const int cbase = ngrp * 16;            // cols 0,16,32,48

    // ---- Stage fp16 W + vectors (once per CTA) ----
    #pragma unroll
    for (int i = tid; i < 128 * WS2 / 4; i += 256)
        ((uint4*)Wh)[i] = ((const uint4*)g_Wh2)[i];
    if (tid < NPAD) { us[tid] = g_up[tid]; bs[tid] = g_bp[tid]; }

    auto prefetch = [&](int c, int bufidx) {
        const float* xg = x + ((size_t)(c >> 7) * T_LEN + (size_t)(c & (CPB - 1)) * CH) * D_DIM;
        float* dst = xs + bufidx * (CH * XS);
        #pragma unroll
        for (int j = 0; j < 8; j++) {
            int i  = j * 256 + tid;          // float4 index within 32x256 tile
            int r  = i >> 6;
            int c4 = i & 63;
            uint32_t sa = (uint32_t)__cvta_generic_to_shared(dst + r * XS + c4 * 4);
            const float4* src = (const float4*)xg + (size_t)r * 64 + c4;
            asm volatile("cp.async.cg.shared.global [%0], [%1], 16;" :: "r"(sa), "l"(src));
        }
        asm volatile("cp.async.commit_group;");
    };

    int c0 = blockIdx.x;
    prefetch(c0, 0);

    int it = 0;
    for (int c = c0; c < NCHUNK; c += GRID, it++) {
        const int nb = it & 1;
        const int cn = c + GRID;
        if (cn < NCHUNK) {
            prefetch(cn, nb ^ 1);
            asm volatile("cp.async.wait_group 1;" ::: "memory");
        } else {
            asm volatile("cp.async.wait_group 0;" ::: "memory");
        }
        __syncthreads();

        const float* cur = xs + nb * (CH * XS);
        const int b = c >> 7;

        // ---- Phase 2: fp16 MMA; 8 warps = 2 m-halves x 4 col-groups (2,2,2,1 tiles)
        if (ngrp < 3) phase2<2>(cur, Wh, us, bs, pt + ngrp * 32, mrow, cbase, g, t);
        else          phase2<1>(cur, Wh, us, bs, pt + 3   * 32, mrow, cbase, g, t);
        __syncthreads();

        // ---- exp + denominator (warp 0; 32 rows exactly) ----
        if (warp == 0) {
            float e = __expf(pt[lane] + pt[32 + lane] + pt[64 + lane] + pt[96 + lane]);
            es[lane] = e;
            float s = e;
            #pragma unroll
            for (int o = 16; o > 0; o >>= 1) s += __shfl_xor_sync(0xFFFFFFFFu, s, o);
            if (lane == 0) atomicAdd(&g_denom[b], s);
        }
        __syncthreads();

        // ---- Phase 3: weighted sum over 32 rows, exact fp32 x from SMEM ----
        float q0 = 0.f, q1 = 0.f, q2 = 0.f, q3 = 0.f;
        #pragma unroll 8
        for (int r = 0; r < CH; r += 4) {
            q0 += es[r + 0] * cur[(r + 0) * XS + tid];
            q1 += es[r + 1] * cur[(r + 1) * XS + tid];
            q2 += es[r + 2] * cur[(r + 2) * XS + tid];
            q3 += es[r + 3] * cur[(r + 3) * XS + tid];
        }
        atomicAdd(&out[b * D_DIM + tid], (q0 + q1) + (q2 + q3));

        __syncthreads();  // buffer + es/pt reuse before next prefetch overwrites
    }
}

__global__ void norm_kernel(float* __restrict__ out) {
    int i = blockIdx.x * blockDim.x + threadIdx.x;
    if (i < NBATCH * D_DIM) {
        out[i] = out[i] / (g_denom[i >> 8] + EPS);
    }
}

extern "C" void kernel_launch(void* const* d_in, const int* in_sizes, int n_in,
                              void* d_out, int out_size) {
    const float* x = (const float*)d_in[0];
    const float* W = (const float*)d_in[1];
    const float* b = (const float*)d_in[2];
    const float* u = (const float*)d_in[3];
    float* out = (float*)d_out;

    const int smem_bytes = (2 * CH * XS) * 4 + (128 * WS2) * 4
                         + (2 * NPAD + CH + 4 * 32) * 4;
    cudaFuncSetAttribute(att_main_kernel,
                         cudaFuncAttributeMaxDynamicSharedMemorySize, smem_bytes);

    prep_kernel<<<(NBATCH * D_DIM + 255) / 256, 256>>>(W, b, u, out);
    att_main_kernel<<<GRID, 256, smem_bytes>>>(x, out);
    norm_kernel<<<(NBATCH * D_DIM + 255) / 256, 256>>>(out);
}